// round 3
// baseline (speedup 1.0000x reference)
#include <cuda_runtime.h>

// Problem constants (fixed by the reference)
#define BB   4
#define SS   2048
#define DD   512
#define HH   8
#define DHD  64
#define MR   (BB * SS)        // 8192 rows
#define SCALE 0.125f          // 1/sqrt(64)

// Attention smem layout (dynamic): Qt[64][65], KPt[64][65], Vs[64][64]
#define QT_STRIDE 65
#define KP_STRIDE 65
#define QT_ELEMS  (64 * QT_STRIDE)
#define KP_ELEMS  (64 * KP_STRIDE)
#define VS_ELEMS  (64 * 64)
#define ATTN_SMEM_BYTES ((QT_ELEMS + KP_ELEMS + VS_ELEMS) * sizeof(float))

// Scratch (no allocations allowed -> __device__ globals), 4 x 16 MB
__device__ float g_Q[(size_t)MR * DD];
__device__ float g_K[(size_t)MR * DD];
__device__ float g_V[(size_t)MR * DD];
__device__ float g_A[(size_t)MR * DD];

// ---------------------------------------------------------------------------
// C[M,N] = A[M,K] @ W[N,K]^T + bias[N]   (M=8192, N=K=512)
// 64x64 block tile, 256 threads, 4x4 per-thread frags, BK=16
// ---------------------------------------------------------------------------
__global__ __launch_bounds__(256) void gemm_tn_bias(
    const float* __restrict__ A, const float* __restrict__ W,
    const float* __restrict__ bias, float* __restrict__ C) {
    const int Kd = DD, Nd = DD;
    __shared__ float As[16][65];   // [k][m]
    __shared__ float Ws[16][65];   // [k][n]
    const int tid = threadIdx.x;
    const int ty = tid >> 4, tx = tid & 15;
    const int m0 = blockIdx.y << 6, n0 = blockIdx.x << 6;
    const int lr = tid >> 2;            // 0..63 row within tile
    const int lc = (tid & 3) << 2;      // 0,4,8,12 k offset
    const float* Ap = A + (size_t)(m0 + lr) * Kd + lc;
    const float* Wp = W + (size_t)(n0 + lr) * Kd + lc;
    float acc[4][4] = {};
    for (int k0 = 0; k0 < Kd; k0 += 16) {
        float4 av = *(const float4*)(Ap + k0);
        float4 wv = *(const float4*)(Wp + k0);
        As[lc + 0][lr] = av.x; As[lc + 1][lr] = av.y;
        As[lc + 2][lr] = av.z; As[lc + 3][lr] = av.w;
        Ws[lc + 0][lr] = wv.x; Ws[lc + 1][lr] = wv.y;
        Ws[lc + 2][lr] = wv.z; Ws[lc + 3][lr] = wv.w;
        __syncthreads();
#pragma unroll
        for (int k = 0; k < 16; k++) {
            float a[4], b[4];
#pragma unroll
            for (int i = 0; i < 4; i++) a[i] = As[k][(ty << 2) + i];
#pragma unroll
            for (int j = 0; j < 4; j++) b[j] = Ws[k][(tx << 2) + j];
#pragma unroll
            for (int i = 0; i < 4; i++)
#pragma unroll
                for (int j = 0; j < 4; j++) acc[i][j] += a[i] * b[j];
        }
        __syncthreads();
    }
    float4 bs = *(const float4*)&bias[n0 + (tx << 2)];
#pragma unroll
    for (int i = 0; i < 4; i++) {
        float4 o;
        o.x = acc[i][0] + bs.x; o.y = acc[i][1] + bs.y;
        o.z = acc[i][2] + bs.z; o.w = acc[i][3] + bs.w;
        *(float4*)&C[(size_t)(m0 + (ty << 2) + i) * Nd + n0 + (tx << 2)] = o;
    }
}

// ---------------------------------------------------------------------------
// Flash attention (causal), fp32, online softmax.
// Block: 256 threads handle 64 queries of one (b,h). Q,K,V laid out as
// [B*S, 512] with head h at column h*64 (no transpose pass needed).
// Dynamic smem (49664 B):
//   Qt  [d=64][q=64]  stride 65  (pre-scaled by 1/sqrt(Dh))
//   KPt [d=64][k=64]  stride 65  (reused as P^T [k][q] for the P@V GEMM)
//   Vs  [k=64][d=64]  stride 64
// ---------------------------------------------------------------------------
__global__ __launch_bounds__(256) void attn_kernel(
    const float* __restrict__ Q, const float* __restrict__ K,
    const float* __restrict__ V, float* __restrict__ O) {
    extern __shared__ float smem[];
    float* Qt  = smem;                       // 64 * 65
    float* KPt = smem + QT_ELEMS;            // 64 * 65
    float* Vs  = smem + QT_ELEMS + KP_ELEMS; // 64 * 64
    const int tid = threadIdx.x;
    const int ty = tid >> 4, tx = tid & 15;
    const int qt = (int)gridDim.x - 1 - (int)blockIdx.x;  // heavy tiles first
    const int h = blockIdx.y, b = blockIdx.z;
    const int q0 = qt << 6;
    const float* Qb = Q + ((size_t)b * SS + q0) * DD + h * DHD;
    const float* Kb = K + ((size_t)b * SS) * DD + h * DHD;
    const float* Vb = V + ((size_t)b * SS) * DD + h * DHD;

    // Load Q tile transposed + scaled (once per block)
    for (int i = tid; i < 1024; i += 256) {
        int r = i >> 4;
        int c = (i & 15) << 2;
        float4 v = *(const float4*)(Qb + (size_t)r * DD + c);
        Qt[(c + 0) * QT_STRIDE + r] = v.x * SCALE;
        Qt[(c + 1) * QT_STRIDE + r] = v.y * SCALE;
        Qt[(c + 2) * QT_STRIDE + r] = v.z * SCALE;
        Qt[(c + 3) * QT_STRIDE + r] = v.w * SCALE;
    }

    float m[4], l[4], o[4][4];
#pragma unroll
    for (int i = 0; i < 4; i++) {
        m[i] = -1e30f; l[i] = 0.f;
#pragma unroll
        for (int j = 0; j < 4; j++) o[i][j] = 0.f;
    }

    const int ntiles = qt + 1;
    for (int t = 0; t < ntiles; t++) {
        const int k0 = t << 6;
        __syncthreads();  // previous P@V / Q load fully consumed
        for (int i = tid; i < 1024; i += 256) {
            int r = i >> 4;
            int c = (i & 15) << 2;
            float4 kv = *(const float4*)(Kb + (size_t)(k0 + r) * DD + c);
            float4 vv = *(const float4*)(Vb + (size_t)(k0 + r) * DD + c);
            KPt[(c + 0) * KP_STRIDE + r] = kv.x;
            KPt[(c + 1) * KP_STRIDE + r] = kv.y;
            KPt[(c + 2) * KP_STRIDE + r] = kv.z;
            KPt[(c + 3) * KP_STRIDE + r] = kv.w;
            *(float4*)&Vs[(r << 6) + c] = vv;
        }
        __syncthreads();

        // Scores s[i][j] = sum_d Qt[d][4ty+i] * Kt[d][4tx+j]
        float s[4][4] = {};
#pragma unroll 8
        for (int d = 0; d < 64; d++) {
            float a[4], bb[4];
#pragma unroll
            for (int i = 0; i < 4; i++) a[i] = Qt[d * QT_STRIDE + (ty << 2) + i];
#pragma unroll
            for (int j = 0; j < 4; j++) bb[j] = KPt[d * KP_STRIDE + (tx << 2) + j];
#pragma unroll
            for (int i = 0; i < 4; i++)
#pragma unroll
                for (int j = 0; j < 4; j++) s[i][j] += a[i] * bb[j];
        }

        if (t == qt) {  // diagonal tile: causal mask (q0 == k0 here)
#pragma unroll
            for (int i = 0; i < 4; i++)
#pragma unroll
                for (int j = 0; j < 4; j++)
                    if ((tx << 2) + j > (ty << 2) + i) s[i][j] = -1e30f;
        }

        // Online softmax (rows spread across 16 tx lanes; contiguous 16-lane
        // groups, so xor-shuffles 1..8 stay within the group)
        float p[4][4];
#pragma unroll
        for (int i = 0; i < 4; i++) {
            float r0 = fmaxf(fmaxf(s[i][0], s[i][1]), fmaxf(s[i][2], s[i][3]));
#pragma unroll
            for (int off = 1; off < 16; off <<= 1)
                r0 = fmaxf(r0, __shfl_xor_sync(0xffffffffu, r0, off));
            float mn = fmaxf(m[i], r0);
            float corr = __expf(m[i] - mn);
            m[i] = mn;
            float sum = 0.f;
#pragma unroll
            for (int j = 0; j < 4; j++) {
                p[i][j] = __expf(s[i][j] - mn);
                sum += p[i][j];
            }
#pragma unroll
            for (int off = 1; off < 16; off <<= 1)
                sum += __shfl_xor_sync(0xffffffffu, sum, off);
            l[i] = l[i] * corr + sum;
#pragma unroll
            for (int j = 0; j < 4; j++) o[i][j] *= corr;
        }

        __syncthreads();  // K tile fully consumed before overwriting with P^T
#pragma unroll
        for (int i = 0; i < 4; i++)
#pragma unroll
            for (int j = 0; j < 4; j++)
                KPt[((tx << 2) + j) * KP_STRIDE + (ty << 2) + i] = p[i][j];
        __syncthreads();

        // o[i][j] += sum_k Pt[k][4ty+i] * Vs[k][4tx+j]
#pragma unroll 8
        for (int k = 0; k < 64; k++) {
            float a[4];
#pragma unroll
            for (int i = 0; i < 4; i++) a[i] = KPt[k * KP_STRIDE + (ty << 2) + i];
            float4 bv = *(const float4*)&Vs[(k << 6) + (tx << 2)];
            float bb[4] = {bv.x, bv.y, bv.z, bv.w};
#pragma unroll
            for (int i = 0; i < 4; i++)
#pragma unroll
                for (int j = 0; j < 4; j++) o[i][j] += a[i] * bb[j];
        }
    }

    // Normalize and write out (same [B*S, 512] layout, head column offset)
#pragma unroll
    for (int i = 0; i < 4; i++) {
        float inv = 1.0f / l[i];
        float4 ov;
        ov.x = o[i][0] * inv; ov.y = o[i][1] * inv;
        ov.z = o[i][2] * inv; ov.w = o[i][3] * inv;
        *(float4*)&O[((size_t)b * SS + q0 + (ty << 2) + i) * DD + h * DHD +
                     (tx << 2)] = ov;
    }
}

// ---------------------------------------------------------------------------
extern "C" void kernel_launch(void* const* d_in, const int* in_sizes, int n_in,
                              void* d_out, int out_size) {
    const float* x  = (const float*)d_in[0];
    // d_in[1] = mask (bool) — causal mask is known statically, ignored
    const float* Wq = (const float*)d_in[2];
    const float* bq = (const float*)d_in[3];
    const float* Wk = (const float*)d_in[4];
    const float* bk = (const float*)d_in[5];
    const float* Wv = (const float*)d_in[6];
    const float* bv = (const float*)d_in[7];
    const float* Wo = (const float*)d_in[8];
    const float* bo = (const float*)d_in[9];
    float* out = (float*)d_out;

    float *qp, *kp, *vp, *ap;
    cudaGetSymbolAddress((void**)&qp, g_Q);
    cudaGetSymbolAddress((void**)&kp, g_K);
    cudaGetSymbolAddress((void**)&vp, g_V);
    cudaGetSymbolAddress((void**)&ap, g_A);

    // Allow >48KB dynamic smem for the attention kernel (idempotent).
    cudaFuncSetAttribute(attn_kernel,
                         cudaFuncAttributeMaxDynamicSharedMemorySize,
                         (int)ATTN_SMEM_BYTES);

    dim3 gg(DD / 64, MR / 64);  // (8, 128)
    gemm_tn_bias<<<gg, 256>>>(x, Wq, bq, qp);
    gemm_tn_bias<<<gg, 256>>>(x, Wk, bk, kp);
    gemm_tn_bias<<<gg, 256>>>(x, Wv, bv, vp);

    dim3 ga(SS / 64, HH, BB);   // (32, 8, 4)
    attn_kernel<<<ga, 256, ATTN_SMEM_BYTES>>>(qp, kp, vp, ap);

    gemm_tn_bias<<<gg, 256>>>(ap, Wo, bo, out);
}

// round 5
// speedup vs baseline: 1.3944x; 1.3944x over previous
#include <cuda_runtime.h>
#include <cuda_bf16.h>
#include <cstdint>

// Problem constants (fixed by the reference)
#define BB   4
#define SS   2048
#define DD   512
#define HH   8
#define DHD  64
#define MR   (BB * SS)        // 8192 rows
#define SCALE 0.125f          // 1/sqrt(64)

// ---------------- scratch (device globals; no allocs allowed) ---------------
__device__ float g_Q[(size_t)MR * DD];
__device__ float g_K[(size_t)MR * DD];
__device__ float g_V[(size_t)MR * DD];
__device__ float g_A[(size_t)MR * DD];
__device__ __align__(16) __nv_bfloat16 g_Xh[(size_t)MR * DD];
__device__ __align__(16) __nv_bfloat16 g_Xl[(size_t)MR * DD];
__device__ __align__(16) __nv_bfloat16 g_Wh[4 * DD * DD];
__device__ __align__(16) __nv_bfloat16 g_Wl[4 * DD * DD];

// ---------------- helpers ---------------------------------------------------
__device__ __forceinline__ uint32_t smem_u32(const void* p) {
    uint32_t a;
    asm("{ .reg .u64 t; cvta.to.shared.u64 t, %1; cvt.u32.u64 %0, t; }"
        : "=r"(a) : "l"(p));
    return a;
}

#define SWZ128(o) ((o) ^ (((o) >> 3) & 0x70))

#define LDSM4(R, addr)                                                        \
    asm volatile("ldmatrix.sync.aligned.m8n8.x4.shared.b16 "                  \
                 "{%0, %1, %2, %3}, [%4];"                                    \
                 : "=r"((R)[0]), "=r"((R)[1]), "=r"((R)[2]), "=r"((R)[3])     \
                 : "r"(addr))

#define MMA_BF16(c, a, b0, b1)                                                \
    asm volatile("mma.sync.aligned.m16n8k16.row.col.f32.bf16.bf16.f32 "       \
                 "{%0, %1, %2, %3}, {%4, %5, %6, %7}, {%8, %9}, "             \
                 "{%0, %1, %2, %3};"                                          \
                 : "+f"((c)[0]), "+f"((c)[1]), "+f"((c)[2]), "+f"((c)[3])     \
                 : "r"((a)[0]), "r"((a)[1]), "r"((a)[2]), "r"((a)[3]),        \
                   "r"(b0), "r"(b1))

// ---------------------------------------------------------------------------
// fp32 -> (hi, lo) bf16 split, float4-vectorized.
// ---------------------------------------------------------------------------
__global__ __launch_bounds__(256) void split_bf16(
    const float* __restrict__ in, __nv_bfloat16* __restrict__ hi,
    __nv_bfloat16* __restrict__ lo, int n4) {
    int i = blockIdx.x * blockDim.x + threadIdx.x;
    if (i >= n4) return;
    float4 v = ((const float4*)in)[i];
    __nv_bfloat16 h0 = __float2bfloat16(v.x);
    __nv_bfloat16 h1 = __float2bfloat16(v.y);
    __nv_bfloat16 h2 = __float2bfloat16(v.z);
    __nv_bfloat16 h3 = __float2bfloat16(v.w);
    __nv_bfloat16 l0 = __float2bfloat16(v.x - __bfloat162float(h0));
    __nv_bfloat16 l1 = __float2bfloat16(v.y - __bfloat162float(h1));
    __nv_bfloat16 l2 = __float2bfloat16(v.z - __bfloat162float(h2));
    __nv_bfloat16 l3 = __float2bfloat16(v.w - __bfloat162float(h3));
    __nv_bfloat162* hp = (__nv_bfloat162*)hi;
    __nv_bfloat162* lp = (__nv_bfloat162*)lo;
    hp[2 * i]     = __halves2bfloat162(h0, h1);
    hp[2 * i + 1] = __halves2bfloat162(h2, h3);
    lp[2 * i]     = __halves2bfloat162(l0, l1);
    lp[2 * i + 1] = __halves2bfloat162(l2, l3);
}

// ---------------------------------------------------------------------------
// mma.sync bf16 3-term GEMM: C[M,N] = (Ah+Al)[M,K] @ (Bh+Bl)[N,K]^T + bias
// CTA: 128x64 tile, 256 thr = 8 warps (4 along M x 2 along N), warp 32x32.
// K staged 64 wide in smem (SW128-swizzled 128B rows), 48 KB total.
// ---------------------------------------------------------------------------
#define GS_A_H 0
#define GS_A_L 16384
#define GS_B_H 32768
#define GS_B_L 40960
#define GS_TOTAL 49152

__global__ __launch_bounds__(256) void gemm_mma_bf16x3(
    const __nv_bfloat16* __restrict__ Ah, const __nv_bfloat16* __restrict__ Al,
    const __nv_bfloat16* __restrict__ Bh, const __nv_bfloat16* __restrict__ Bl,
    const float* __restrict__ bias, float* __restrict__ C) {
    extern __shared__ char smem[];
    const uint32_t sb = smem_u32(smem);
    const int tid = threadIdx.x;
    const int wid = tid >> 5, lane = tid & 31;
    const int wm = wid & 3, wn = wid >> 2;   // warp coords: 4 x 2
    const int m0 = (int)blockIdx.y << 7;     // 128-row tile
    const int n0 = (int)blockIdx.x << 6;     // 64-col tile

    float acc[2][4][4] = {};

    // Per-lane ldmatrix address components (element offsets within tile)
    const int a_row = (lane & 15);            // + wm*32 + t*16
    const int a_koff = (lane >> 4) << 3;      // 0 or 8
    const int b_mi  = lane >> 3;              // 0..3
    const int b_r   = lane & 7;
    const int b_jo  = b_mi >> 1;              // 0/1 within pair
    const int b_koff = (b_mi & 1) << 3;       // 0 or 8

    for (int c = 0; c < 8; c++) {
        const int kc = c << 6;
        __syncthreads();  // previous iter's smem fully consumed
        // Stage A (128 rows x 64 bf16 = 128 B/row): 1024 uint4 per matrix
        for (int v = tid; v < 1024; v += 256) {
            int r = v >> 3, cv = v & 7;
            size_t go = ((size_t)(m0 + r) * DD + kc) * 2 + (size_t)cv * 16;
            uint32_t bo = SWZ128((uint32_t)(r * 128 + cv * 16));
            *(uint4*)(smem + GS_A_H + bo) = *(const uint4*)((const char*)Ah + go);
            *(uint4*)(smem + GS_A_L + bo) = *(const uint4*)((const char*)Al + go);
        }
        // Stage B (64 rows): 512 uint4 per matrix
        for (int v = tid; v < 512; v += 256) {
            int r = v >> 3, cv = v & 7;
            size_t go = ((size_t)(n0 + r) * DD + kc) * 2 + (size_t)cv * 16;
            uint32_t bo = SWZ128((uint32_t)(r * 128 + cv * 16));
            *(uint4*)(smem + GS_B_H + bo) = *(const uint4*)((const char*)Bh + go);
            *(uint4*)(smem + GS_B_L + bo) = *(const uint4*)((const char*)Bl + go);
        }
        __syncthreads();

#pragma unroll
        for (int ks = 0; ks < 4; ks++) {
            const int kb = ks << 4;
            // A fragments (hi + lo) for the 2 m16 tiles
            uint32_t ah[2][4], al[2][4];
#pragma unroll
            for (int t = 0; t < 2; t++) {
                int row = wm * 32 + t * 16 + a_row;
                uint32_t off = SWZ128((uint32_t)(row * 128 + (kb + a_koff) * 2));
                LDSM4(ah[t], sb + GS_A_H + off);
                LDSM4(al[t], sb + GS_A_L + off);
            }
            // B fragments (hi + lo) for the 4 n8 tiles (two x4 loads each)
            uint32_t bh[4][2], bl[4][2];
#pragma unroll
            for (int p = 0; p < 2; p++) {
                int j = p * 2 + b_jo;
                int row = wn * 32 + j * 8 + b_r;
                uint32_t off = SWZ128((uint32_t)(row * 128 + (kb + b_koff) * 2));
                uint32_t R[4];
                LDSM4(R, sb + GS_B_H + off);
                bh[p * 2 + 0][0] = R[0]; bh[p * 2 + 0][1] = R[1];
                bh[p * 2 + 1][0] = R[2]; bh[p * 2 + 1][1] = R[3];
                LDSM4(R, sb + GS_B_L + off);
                bl[p * 2 + 0][0] = R[0]; bl[p * 2 + 0][1] = R[1];
                bl[p * 2 + 1][0] = R[2]; bl[p * 2 + 1][1] = R[3];
            }
#pragma unroll
            for (int t = 0; t < 2; t++)
#pragma unroll
                for (int j = 0; j < 4; j++) {
                    MMA_BF16(acc[t][j], ah[t], bh[j][0], bh[j][1]);
                    MMA_BF16(acc[t][j], al[t], bh[j][0], bh[j][1]);
                    MMA_BF16(acc[t][j], ah[t], bl[j][0], bl[j][1]);
                }
        }
    }

    // Epilogue: frag (t,j): rows m = wm*32+t*16+lane/4 (+8), cols n = j*8+(lane%4)*2
#pragma unroll
    for (int t = 0; t < 2; t++) {
        int row = m0 + wm * 32 + t * 16 + (lane >> 2);
#pragma unroll
        for (int j = 0; j < 4; j++) {
            int col = n0 + wn * 32 + j * 8 + ((lane & 3) << 1);
            float b0 = bias[col], b1 = bias[col + 1];
            float2 v0 = {acc[t][j][0] + b0, acc[t][j][1] + b1};
            float2 v1 = {acc[t][j][2] + b0, acc[t][j][3] + b1};
            *(float2*)&C[(size_t)row * DD + col] = v0;
            *(float2*)&C[(size_t)(row + 8) * DD + col] = v1;
        }
    }
}

// ---------------------------------------------------------------------------
// Flash attention (causal), fp32, online softmax. Unchanged from R3 pass.
// Dynamic smem 49664 B: Qt[64][65], KPt[64][65] (reused as P^T), Vs[64][64].
// ---------------------------------------------------------------------------
#define QT_STRIDE 65
#define KP_STRIDE 65
#define QT_ELEMS  (64 * QT_STRIDE)
#define KP_ELEMS  (64 * KP_STRIDE)
#define VS_ELEMS  (64 * 64)
#define ATTN_SMEM_BYTES ((QT_ELEMS + KP_ELEMS + VS_ELEMS) * sizeof(float))

__global__ __launch_bounds__(256) void attn_kernel(
    const float* __restrict__ Q, const float* __restrict__ K,
    const float* __restrict__ V, float* __restrict__ O) {
    extern __shared__ float smemf[];
    float* Qt  = smemf;
    float* KPt = smemf + QT_ELEMS;
    float* Vs  = smemf + QT_ELEMS + KP_ELEMS;
    const int tid = threadIdx.x;
    const int ty = tid >> 4, tx = tid & 15;
    const int qt = (int)gridDim.x - 1 - (int)blockIdx.x;  // heavy tiles first
    const int h = blockIdx.y, b = blockIdx.z;
    const int q0 = qt << 6;
    const float* Qb = Q + ((size_t)b * SS + q0) * DD + h * DHD;
    const float* Kb = K + ((size_t)b * SS) * DD + h * DHD;
    const float* Vb = V + ((size_t)b * SS) * DD + h * DHD;

    for (int i = tid; i < 1024; i += 256) {
        int r = i >> 4;
        int c = (i & 15) << 2;
        float4 v = *(const float4*)(Qb + (size_t)r * DD + c);
        Qt[(c + 0) * QT_STRIDE + r] = v.x * SCALE;
        Qt[(c + 1) * QT_STRIDE + r] = v.y * SCALE;
        Qt[(c + 2) * QT_STRIDE + r] = v.z * SCALE;
        Qt[(c + 3) * QT_STRIDE + r] = v.w * SCALE;
    }

    float m[4], l[4], o[4][4];
#pragma unroll
    for (int i = 0; i < 4; i++) {
        m[i] = -1e30f; l[i] = 0.f;
#pragma unroll
        for (int j = 0; j < 4; j++) o[i][j] = 0.f;
    }

    const int ntiles = qt + 1;
    for (int t = 0; t < ntiles; t++) {
        const int k0 = t << 6;
        __syncthreads();
        for (int i = tid; i < 1024; i += 256) {
            int r = i >> 4;
            int c = (i & 15) << 2;
            float4 kv = *(const float4*)(Kb + (size_t)(k0 + r) * DD + c);
            float4 vv = *(const float4*)(Vb + (size_t)(k0 + r) * DD + c);
            KPt[(c + 0) * KP_STRIDE + r] = kv.x;
            KPt[(c + 1) * KP_STRIDE + r] = kv.y;
            KPt[(c + 2) * KP_STRIDE + r] = kv.z;
            KPt[(c + 3) * KP_STRIDE + r] = kv.w;
            *(float4*)&Vs[(r << 6) + c] = vv;
        }
        __syncthreads();

        float s[4][4] = {};
#pragma unroll 8
        for (int d = 0; d < 64; d++) {
            float a[4], bb[4];
#pragma unroll
            for (int i = 0; i < 4; i++) a[i] = Qt[d * QT_STRIDE + (ty << 2) + i];
#pragma unroll
            for (int j = 0; j < 4; j++) bb[j] = KPt[d * KP_STRIDE + (tx << 2) + j];
#pragma unroll
            for (int i = 0; i < 4; i++)
#pragma unroll
                for (int j = 0; j < 4; j++) s[i][j] += a[i] * bb[j];
        }

        if (t == qt) {
#pragma unroll
            for (int i = 0; i < 4; i++)
#pragma unroll
                for (int j = 0; j < 4; j++)
                    if ((tx << 2) + j > (ty << 2) + i) s[i][j] = -1e30f;
        }

        float p[4][4];
#pragma unroll
        for (int i = 0; i < 4; i++) {
            float r0 = fmaxf(fmaxf(s[i][0], s[i][1]), fmaxf(s[i][2], s[i][3]));
#pragma unroll
            for (int off = 1; off < 16; off <<= 1)
                r0 = fmaxf(r0, __shfl_xor_sync(0xffffffffu, r0, off));
            float mn = fmaxf(m[i], r0);
            float corr = __expf(m[i] - mn);
            m[i] = mn;
            float sum = 0.f;
#pragma unroll
            for (int j = 0; j < 4; j++) {
                p[i][j] = __expf(s[i][j] - mn);
                sum += p[i][j];
            }
#pragma unroll
            for (int off = 1; off < 16; off <<= 1)
                sum += __shfl_xor_sync(0xffffffffu, sum, off);
            l[i] = l[i] * corr + sum;
#pragma unroll
            for (int j = 0; j < 4; j++) o[i][j] *= corr;
        }

        __syncthreads();
#pragma unroll
        for (int i = 0; i < 4; i++)
#pragma unroll
            for (int j = 0; j < 4; j++)
                KPt[((tx << 2) + j) * KP_STRIDE + (ty << 2) + i] = p[i][j];
        __syncthreads();

#pragma unroll 8
        for (int k = 0; k < 64; k++) {
            float a[4];
#pragma unroll
            for (int i = 0; i < 4; i++) a[i] = KPt[k * KP_STRIDE + (ty << 2) + i];
            float4 bv = *(const float4*)&Vs[(k << 6) + (tx << 2)];
            float bb[4] = {bv.x, bv.y, bv.z, bv.w};
#pragma unroll
            for (int i = 0; i < 4; i++)
#pragma unroll
                for (int j = 0; j < 4; j++) o[i][j] += a[i] * bb[j];
        }
    }

#pragma unroll
    for (int i = 0; i < 4; i++) {
        float inv = 1.0f / l[i];
        float4 ov;
        ov.x = o[i][0] * inv; ov.y = o[i][1] * inv;
        ov.z = o[i][2] * inv; ov.w = o[i][3] * inv;
        *(float4*)&O[((size_t)b * SS + q0 + (ty << 2) + i) * DD + h * DHD +
                     (tx << 2)] = ov;
    }
}

// ---------------------------------------------------------------------------
extern "C" void kernel_launch(void* const* d_in, const int* in_sizes, int n_in,
                              void* d_out, int out_size) {
    const float* x  = (const float*)d_in[0];
    const float* Wq = (const float*)d_in[2];
    const float* bq = (const float*)d_in[3];
    const float* Wk = (const float*)d_in[4];
    const float* bk = (const float*)d_in[5];
    const float* Wv = (const float*)d_in[6];
    const float* bv = (const float*)d_in[7];
    const float* Wo = (const float*)d_in[8];
    const float* bo = (const float*)d_in[9];
    float* out = (float*)d_out;

    float *qp, *kp, *vp, *ap;
    __nv_bfloat16 *xh, *xl, *wh, *wl;
    cudaGetSymbolAddress((void**)&qp, g_Q);
    cudaGetSymbolAddress((void**)&kp, g_K);
    cudaGetSymbolAddress((void**)&vp, g_V);
    cudaGetSymbolAddress((void**)&ap, g_A);
    cudaGetSymbolAddress((void**)&xh, g_Xh);
    cudaGetSymbolAddress((void**)&xl, g_Xl);
    cudaGetSymbolAddress((void**)&wh, g_Wh);
    cudaGetSymbolAddress((void**)&wl, g_Wl);

    cudaFuncSetAttribute(attn_kernel,
                         cudaFuncAttributeMaxDynamicSharedMemorySize,
                         (int)ATTN_SMEM_BYTES);
    cudaFuncSetAttribute(gemm_mma_bf16x3,
                         cudaFuncAttributeMaxDynamicSharedMemorySize, GS_TOTAL);

    const int NX4 = MR * DD / 4;      // 1M float4
    const int NW4 = DD * DD / 4;      // 64K float4

    // Split x and the four weights into bf16 hi/lo
    split_bf16<<<(NX4 + 255) / 256, 256>>>(x, xh, xl, NX4);
    split_bf16<<<(NW4 + 255) / 256, 256>>>(Wq, wh + 0 * DD * DD, wl + 0 * DD * DD, NW4);
    split_bf16<<<(NW4 + 255) / 256, 256>>>(Wk, wh + 1 * DD * DD, wl + 1 * DD * DD, NW4);
    split_bf16<<<(NW4 + 255) / 256, 256>>>(Wv, wh + 2 * DD * DD, wl + 2 * DD * DD, NW4);
    split_bf16<<<(NW4 + 255) / 256, 256>>>(Wo, wh + 3 * DD * DD, wl + 3 * DD * DD, NW4);

    dim3 gg(DD / 64, MR / 128);  // (8, 64)
    gemm_mma_bf16x3<<<gg, 256, GS_TOTAL>>>(xh, xl, wh + 0 * DD * DD, wl + 0 * DD * DD, bq, qp);
    gemm_mma_bf16x3<<<gg, 256, GS_TOTAL>>>(xh, xl, wh + 1 * DD * DD, wl + 1 * DD * DD, bk, kp);
    gemm_mma_bf16x3<<<gg, 256, GS_TOTAL>>>(xh, xl, wh + 2 * DD * DD, wl + 2 * DD * DD, bv, vp);

    dim3 ga(SS / 64, HH, BB);   // (32, 8, 4)
    attn_kernel<<<ga, 256, ATTN_SMEM_BYTES>>>(qp, kp, vp, ap);

    // Split attention output (x buffers no longer needed) and run O projection
    split_bf16<<<(NX4 + 255) / 256, 256>>>(ap, xh, xl, NX4);
    gemm_mma_bf16x3<<<gg, 256, GS_TOTAL>>>(xh, xl, wh + 3 * DD * DD, wl + 3 * DD * DD, bo, out);
}

// round 9
// speedup vs baseline: 2.7593x; 1.9788x over previous
#include <cuda_runtime.h>
#include <cuda_bf16.h>
#include <cstdint>

// Problem constants (fixed by the reference)
#define BB   4
#define SS   2048
#define DD   512
#define HH   8
#define DHD  64
#define MR   (BB * SS)        // 8192 rows
#define SCALE 0.125f          // 1/sqrt(64)

// ---------------- scratch (device globals; no allocs allowed) ---------------
__device__ __align__(16) __nv_bfloat16 g_Xh[(size_t)MR * DD];
__device__ __align__(16) __nv_bfloat16 g_Xl[(size_t)MR * DD];
__device__ __align__(16) __nv_bfloat16 g_Qh[(size_t)MR * DD];
__device__ __align__(16) __nv_bfloat16 g_Ql[(size_t)MR * DD];
__device__ __align__(16) __nv_bfloat16 g_Kh[(size_t)MR * DD];
__device__ __align__(16) __nv_bfloat16 g_Kl[(size_t)MR * DD];
__device__ __align__(16) __nv_bfloat16 g_Vh[(size_t)MR * DD];
__device__ __align__(16) __nv_bfloat16 g_Vl[(size_t)MR * DD];
__device__ __align__(16) __nv_bfloat16 g_Wh[4 * DD * DD];
__device__ __align__(16) __nv_bfloat16 g_Wl[4 * DD * DD];

// ---------------- helpers ---------------------------------------------------
__device__ __forceinline__ uint32_t smem_u32(const void* p) {
    uint32_t a;
    asm("{ .reg .u64 t; cvta.to.shared.u64 t, %1; cvt.u32.u64 %0, t; }"
        : "=r"(a) : "l"(p));
    return a;
}

#define SWZ128(o) ((o) ^ (((o) >> 3) & 0x70))

#define LDSM4(R, addr)                                                        \
    asm volatile("ldmatrix.sync.aligned.m8n8.x4.shared.b16 "                  \
                 "{%0, %1, %2, %3}, [%4];"                                    \
                 : "=r"((R)[0]), "=r"((R)[1]), "=r"((R)[2]), "=r"((R)[3])     \
                 : "r"(addr))

#define LDSM4T(R, addr)                                                       \
    asm volatile("ldmatrix.sync.aligned.m8n8.x4.trans.shared.b16 "            \
                 "{%0, %1, %2, %3}, [%4];"                                    \
                 : "=r"((R)[0]), "=r"((R)[1]), "=r"((R)[2]), "=r"((R)[3])     \
                 : "r"(addr))

#define MMA_BF16(c, a, b0, b1)                                                \
    asm volatile("mma.sync.aligned.m16n8k16.row.col.f32.bf16.bf16.f32 "       \
                 "{%0, %1, %2, %3}, {%4, %5, %6, %7}, {%8, %9}, "             \
                 "{%0, %1, %2, %3};"                                          \
                 : "+f"((c)[0]), "+f"((c)[1]), "+f"((c)[2]), "+f"((c)[3])     \
                 : "r"((a)[0]), "r"((a)[1]), "r"((a)[2]), "r"((a)[3]),        \
                   "r"(b0), "r"(b1))

__device__ __forceinline__ uint32_t pack_bf2(float a, float b) {
    __nv_bfloat162 t;
    t.x = __float2bfloat16(a);
    t.y = __float2bfloat16(b);
    return *(uint32_t*)&t;
}

// ---------------------------------------------------------------------------
// fp32 -> (hi, lo) bf16 split, float4-vectorized.
// ---------------------------------------------------------------------------
__global__ __launch_bounds__(256) void split_bf16(
    const float* __restrict__ in, __nv_bfloat16* __restrict__ hi,
    __nv_bfloat16* __restrict__ lo, int n4) {
    int i = blockIdx.x * blockDim.x + threadIdx.x;
    if (i >= n4) return;
    float4 v = ((const float4*)in)[i];
    __nv_bfloat16 h0 = __float2bfloat16(v.x);
    __nv_bfloat16 h1 = __float2bfloat16(v.y);
    __nv_bfloat16 h2 = __float2bfloat16(v.z);
    __nv_bfloat16 h3 = __float2bfloat16(v.w);
    __nv_bfloat16 l0 = __float2bfloat16(v.x - __bfloat162float(h0));
    __nv_bfloat16 l1 = __float2bfloat16(v.y - __bfloat162float(h1));
    __nv_bfloat16 l2 = __float2bfloat16(v.z - __bfloat162float(h2));
    __nv_bfloat16 l3 = __float2bfloat16(v.w - __bfloat162float(h3));
    __nv_bfloat162* hp = (__nv_bfloat162*)hi;
    __nv_bfloat162* lp = (__nv_bfloat162*)lo;
    hp[2 * i]     = __halves2bfloat162(h0, h1);
    hp[2 * i + 1] = __halves2bfloat162(h2, h3);
    lp[2 * i]     = __halves2bfloat162(l0, l1);
    lp[2 * i + 1] = __halves2bfloat162(l2, l3);
}

// ---------------------------------------------------------------------------
// mma.sync bf16 3-term GEMM: C = (Ah+Al)[M,K] @ (Bh+Bl)[N,K]^T + bias, *scale
// CTA: 128x64 tile, 256 thr = 8 warps (4 M x 2 N), warp 32x32.
// BF16OUT: write (hi, lo) bf16 split instead of fp32 (for Q/K/V).
// ---------------------------------------------------------------------------
#define GS_A_H 0
#define GS_A_L 16384
#define GS_B_H 32768
#define GS_B_L 40960
#define GS_TOTAL 49152

template <bool BF16OUT>
__global__ __launch_bounds__(256) void gemm_mma_bf16x3(
    const __nv_bfloat16* __restrict__ Ah, const __nv_bfloat16* __restrict__ Al,
    const __nv_bfloat16* __restrict__ Bh, const __nv_bfloat16* __restrict__ Bl,
    const float* __restrict__ bias, float scale, float* __restrict__ C,
    __nv_bfloat16* __restrict__ Ch, __nv_bfloat16* __restrict__ Cl) {
    extern __shared__ char smem[];
    const uint32_t sb = smem_u32(smem);
    const int tid = threadIdx.x;
    const int wid = tid >> 5, lane = tid & 31;
    const int wm = wid & 3, wn = wid >> 2;
    const int m0 = (int)blockIdx.y << 7;
    const int n0 = (int)blockIdx.x << 6;

    float acc[2][4][4] = {};

    const int a_row = (lane & 15);
    const int a_koff = (lane >> 4) << 3;
    const int b_mi  = lane >> 3;
    const int b_r   = lane & 7;
    const int b_jo  = b_mi >> 1;
    const int b_koff = (b_mi & 1) << 3;

    for (int c = 0; c < 8; c++) {
        const int kc = c << 6;
        __syncthreads();
        for (int v = tid; v < 1024; v += 256) {
            int r = v >> 3, cv = v & 7;
            size_t go = ((size_t)(m0 + r) * DD + kc) * 2 + (size_t)cv * 16;
            uint32_t bo = SWZ128((uint32_t)(r * 128 + cv * 16));
            *(uint4*)(smem + GS_A_H + bo) = *(const uint4*)((const char*)Ah + go);
            *(uint4*)(smem + GS_A_L + bo) = *(const uint4*)((const char*)Al + go);
        }
        for (int v = tid; v < 512; v += 256) {
            int r = v >> 3, cv = v & 7;
            size_t go = ((size_t)(n0 + r) * DD + kc) * 2 + (size_t)cv * 16;
            uint32_t bo = SWZ128((uint32_t)(r * 128 + cv * 16));
            *(uint4*)(smem + GS_B_H + bo) = *(const uint4*)((const char*)Bh + go);
            *(uint4*)(smem + GS_B_L + bo) = *(const uint4*)((const char*)Bl + go);
        }
        __syncthreads();

#pragma unroll
        for (int ks = 0; ks < 4; ks++) {
            const int kb = ks << 4;
            uint32_t ah[2][4], al[2][4];
#pragma unroll
            for (int t = 0; t < 2; t++) {
                int row = wm * 32 + t * 16 + a_row;
                uint32_t off = SWZ128((uint32_t)(row * 128 + (kb + a_koff) * 2));
                LDSM4(ah[t], sb + GS_A_H + off);
                LDSM4(al[t], sb + GS_A_L + off);
            }
#pragma unroll
            for (int p = 0; p < 2; p++) {
                int j = p * 2 + b_jo;
                int row = wn * 32 + j * 8 + b_r;
                uint32_t off = SWZ128((uint32_t)(row * 128 + (kb + b_koff) * 2));
                uint32_t BH[4], BL[4];
                LDSM4(BH, sb + GS_B_H + off);
                LDSM4(BL, sb + GS_B_L + off);
                int j0 = p * 2, j1 = p * 2 + 1;
#pragma unroll
                for (int t = 0; t < 2; t++) {
                    MMA_BF16(acc[t][j0], ah[t], BH[0], BH[1]);
                    MMA_BF16(acc[t][j1], ah[t], BH[2], BH[3]);
                    MMA_BF16(acc[t][j0], al[t], BH[0], BH[1]);
                    MMA_BF16(acc[t][j1], al[t], BH[2], BH[3]);
                    MMA_BF16(acc[t][j0], ah[t], BL[0], BL[1]);
                    MMA_BF16(acc[t][j1], ah[t], BL[2], BL[3]);
                }
            }
        }
    }

#pragma unroll
    for (int t = 0; t < 2; t++) {
        int row = m0 + wm * 32 + t * 16 + (lane >> 2);
#pragma unroll
        for (int j = 0; j < 4; j++) {
            int col = n0 + wn * 32 + j * 8 + ((lane & 3) << 1);
            float b0 = bias[col], b1 = bias[col + 1];
            float v0 = (acc[t][j][0] + b0) * scale;
            float v1 = (acc[t][j][1] + b1) * scale;
            float v2 = (acc[t][j][2] + b0) * scale;
            float v3 = (acc[t][j][3] + b1) * scale;
            if (BF16OUT) {
                __nv_bfloat16 h0 = __float2bfloat16(v0);
                __nv_bfloat16 h1 = __float2bfloat16(v1);
                __nv_bfloat16 h2 = __float2bfloat16(v2);
                __nv_bfloat16 h3 = __float2bfloat16(v3);
                *(uint32_t*)&Ch[(size_t)row * DD + col] =
                    pack_bf2(__bfloat162float(h0) * 0.f + v0, v1);  // hi pair
                // (hi pair written via pack_bf2(v0,v1) — identical rounding)
                *(uint32_t*)&Cl[(size_t)row * DD + col] =
                    pack_bf2(v0 - __bfloat162float(h0), v1 - __bfloat162float(h1));
                *(uint32_t*)&Ch[(size_t)(row + 8) * DD + col] = pack_bf2(v2, v3);
                *(uint32_t*)&Cl[(size_t)(row + 8) * DD + col] =
                    pack_bf2(v2 - __bfloat162float(h2), v3 - __bfloat162float(h3));
            } else {
                float2 o0 = {v0, v1};
                float2 o1 = {v2, v3};
                *(float2*)&C[(size_t)row * DD + col] = o0;
                *(float2*)&C[(size_t)(row + 8) * DD + col] = o1;
            }
        }
    }
}

// ---------------------------------------------------------------------------
// Flash attention (causal) on mma.sync bf16 3-term.
// CTA: 128 queries x one (b,h); 8 warps, each owns 16 rows x all 64 cols.
// Smem (32 KB): Kh/Kl/Vh/Vl 64x64 bf16 tiles (128B rows, SW128).
// Q fragments hoisted to registers (smem reused for K/V after).
// Output written as bf16 hi/lo for the O-projection GEMM.
// ---------------------------------------------------------------------------
#define AS_KH 0
#define AS_KL 8192
#define AS_VH 16384
#define AS_VL 24576

__global__ __launch_bounds__(256) void attn_mma(
    const __nv_bfloat16* __restrict__ Qh, const __nv_bfloat16* __restrict__ Ql,
    const __nv_bfloat16* __restrict__ Kh, const __nv_bfloat16* __restrict__ Kl,
    const __nv_bfloat16* __restrict__ Vh, const __nv_bfloat16* __restrict__ Vl,
    __nv_bfloat16* __restrict__ Oh, __nv_bfloat16* __restrict__ Ol) {
    __shared__ __align__(128) char smem[32768];
    const uint32_t sb = smem_u32(smem);
    const int tid = threadIdx.x;
    const int wid = tid >> 5, lane = tid & 31;
    const int qt = (int)gridDim.x - 1 - (int)blockIdx.x;  // heavy tiles first
    const int h = blockIdx.y, b = blockIdx.z;
    const int q0 = qt << 7;

    const size_t head_off = (size_t)b * SS * DD + h * DHD;
    const __nv_bfloat16* Qhp = Qh + head_off + (size_t)q0 * DD;
    const __nv_bfloat16* Qlp = Ql + head_off + (size_t)q0 * DD;
    const __nv_bfloat16* Khp = Kh + head_off;
    const __nv_bfloat16* Klp = Kl + head_off;
    const __nv_bfloat16* Vhp = Vh + head_off;
    const __nv_bfloat16* Vlp = Vl + head_off;

    // --- Stage Q (128 x 64, hi at [0,16K), lo at [16K,32K)), grab A-frags ---
    for (int v = tid; v < 1024; v += 256) {
        int r = v >> 3, c = v & 7;
        uint32_t bo = SWZ128((uint32_t)(r * 128 + c * 16));
        *(uint4*)(smem + bo) = *(const uint4*)(Qhp + (size_t)r * DD + c * 8);
        *(uint4*)(smem + 16384 + bo) = *(const uint4*)(Qlp + (size_t)r * DD + c * 8);
    }
    __syncthreads();
    uint32_t qh[4][4], ql[4][4];
    {
        const int arow = wid * 16 + (lane & 15);
        const int akoff = (lane >> 4) << 3;
#pragma unroll
        for (int s = 0; s < 4; s++) {
            uint32_t off = SWZ128((uint32_t)(arow * 128 + (s * 16 + akoff) * 2));
            LDSM4(qh[s], sb + off);
            LDSM4(ql[s], sb + 16384 + off);
        }
    }
    __syncthreads();

    const int b_mi = lane >> 3;
    const int b_r = lane & 7;
    const int b_jo = b_mi >> 1;
    const int b_koff = (b_mi & 1) << 3;

    float m0 = -1e30f, m1 = -1e30f, l0 = 0.f, l1 = 0.f;
    float oacc[8][4] = {};

    const int ntiles = 2 * qt + 2;
    for (int t = 0; t < ntiles; t++) {
        const int k0 = t << 6;
        // Stage K/V hi/lo (64 rows x 128B each)
        for (int v = tid; v < 512; v += 256) {
            int r = v >> 3, c = v & 7;
            uint32_t bo = SWZ128((uint32_t)(r * 128 + c * 16));
            size_t g = (size_t)(k0 + r) * DD + c * 8;
            *(uint4*)(smem + AS_KH + bo) = *(const uint4*)(Khp + g);
            *(uint4*)(smem + AS_KL + bo) = *(const uint4*)(Klp + g);
            *(uint4*)(smem + AS_VH + bo) = *(const uint4*)(Vhp + g);
            *(uint4*)(smem + AS_VL + bo) = *(const uint4*)(Vlp + g);
        }
        __syncthreads();

        // ---- S = Q K^T (3-term) ----
        float sacc[8][4] = {};
#pragma unroll
        for (int s = 0; s < 4; s++) {
#pragma unroll
            for (int p = 0; p < 4; p++) {
                int row = p * 16 + b_jo * 8 + b_r;  // key row
                uint32_t off =
                    SWZ128((uint32_t)(row * 128 + (s * 16 + b_koff) * 2));
                uint32_t BH[4], BL[4];
                LDSM4(BH, sb + AS_KH + off);
                LDSM4(BL, sb + AS_KL + off);
                int j0 = p * 2, j1 = p * 2 + 1;
                MMA_BF16(sacc[j0], qh[s], BH[0], BH[1]);
                MMA_BF16(sacc[j1], qh[s], BH[2], BH[3]);
                MMA_BF16(sacc[j0], ql[s], BH[0], BH[1]);
                MMA_BF16(sacc[j1], ql[s], BH[2], BH[3]);
                MMA_BF16(sacc[j0], qh[s], BL[0], BL[1]);
                MMA_BF16(sacc[j1], qh[s], BL[2], BL[3]);
            }
        }

        // ---- causal mask (only the last two tiles touch the diagonal) ----
        if (t >= 2 * qt) {
            const int rbase = wid * 16 + (lane >> 2);
            const int cbase = (lane & 3) << 1;
#pragma unroll
            for (int j = 0; j < 8; j++)
#pragma unroll
                for (int c = 0; c < 4; c++) {
                    int row = rbase + ((c >> 1) << 3);
                    int col = j * 8 + cbase + (c & 1);
                    if (k0 + col > q0 + row) sacc[j][c] = -1e30f;
                }
        }

        // ---- online softmax (rows live in quads; xor 1,2 shuffles) ----
        float rmax0 = -1e30f, rmax1 = -1e30f;
#pragma unroll
        for (int j = 0; j < 8; j++) {
            rmax0 = fmaxf(rmax0, fmaxf(sacc[j][0], sacc[j][1]));
            rmax1 = fmaxf(rmax1, fmaxf(sacc[j][2], sacc[j][3]));
        }
        rmax0 = fmaxf(rmax0, __shfl_xor_sync(0xffffffffu, rmax0, 1));
        rmax0 = fmaxf(rmax0, __shfl_xor_sync(0xffffffffu, rmax0, 2));
        rmax1 = fmaxf(rmax1, __shfl_xor_sync(0xffffffffu, rmax1, 1));
        rmax1 = fmaxf(rmax1, __shfl_xor_sync(0xffffffffu, rmax1, 2));
        float mn0 = fmaxf(m0, rmax0), mn1 = fmaxf(m1, rmax1);
        float corr0 = __expf(m0 - mn0), corr1 = __expf(m1 - mn1);
        m0 = mn0; m1 = mn1;

        float sum0 = 0.f, sum1 = 0.f;
        uint32_t ph[4][4], pl[4][4];
#pragma unroll
        for (int s = 0; s < 4; s++) {
            int j0 = 2 * s, j1 = 2 * s + 1;
            float e00 = __expf(sacc[j0][0] - mn0);
            float e01 = __expf(sacc[j0][1] - mn0);
            float e02 = __expf(sacc[j0][2] - mn1);
            float e03 = __expf(sacc[j0][3] - mn1);
            float e10 = __expf(sacc[j1][0] - mn0);
            float e11 = __expf(sacc[j1][1] - mn0);
            float e12 = __expf(sacc[j1][2] - mn1);
            float e13 = __expf(sacc[j1][3] - mn1);
            sum0 += e00 + e01 + e10 + e11;
            sum1 += e02 + e03 + e12 + e13;
            ph[s][0] = pack_bf2(e00, e01);
            ph[s][1] = pack_bf2(e02, e03);
            ph[s][2] = pack_bf2(e10, e11);
            ph[s][3] = pack_bf2(e12, e13);
            __nv_bfloat162 h0 = *(__nv_bfloat162*)&ph[s][0];
            __nv_bfloat162 h1 = *(__nv_bfloat162*)&ph[s][1];
            __nv_bfloat162 h2 = *(__nv_bfloat162*)&ph[s][2];
            __nv_bfloat162 h3 = *(__nv_bfloat162*)&ph[s][3];
            pl[s][0] = pack_bf2(e00 - __bfloat162float(h0.x),
                                e01 - __bfloat162float(h0.y));
            pl[s][1] = pack_bf2(e02 - __bfloat162float(h1.x),
                                e03 - __bfloat162float(h1.y));
            pl[s][2] = pack_bf2(e10 - __bfloat162float(h2.x),
                                e11 - __bfloat162float(h2.y));
            pl[s][3] = pack_bf2(e12 - __bfloat162float(h3.x),
                                e13 - __bfloat162float(h3.y));
        }
        sum0 += __shfl_xor_sync(0xffffffffu, sum0, 1);
        sum0 += __shfl_xor_sync(0xffffffffu, sum0, 2);
        sum1 += __shfl_xor_sync(0xffffffffu, sum1, 1);
        sum1 += __shfl_xor_sync(0xffffffffu, sum1, 2);
        l0 = l0 * corr0 + sum0;
        l1 = l1 * corr1 + sum1;
#pragma unroll
        for (int j = 0; j < 8; j++) {
            oacc[j][0] *= corr0; oacc[j][1] *= corr0;
            oacc[j][2] *= corr1; oacc[j][3] *= corr1;
        }

        // ---- O += P V (3-term); V via ldmatrix.trans from [key][d] ----
#pragma unroll
        for (int s = 0; s < 4; s++) {
#pragma unroll
            for (int p = 0; p < 4; p++) {
                int krow = s * 16 + ((b_mi & 1) << 3) + b_r;
                int colb = (p * 2 + b_jo) * 16;
                uint32_t off = SWZ128((uint32_t)(krow * 128 + colb));
                uint32_t BH[4], BL[4];
                LDSM4T(BH, sb + AS_VH + off);
                LDSM4T(BL, sb + AS_VL + off);
                int j0 = p * 2, j1 = p * 2 + 1;
                MMA_BF16(oacc[j0], ph[s], BH[0], BH[1]);
                MMA_BF16(oacc[j1], ph[s], BH[2], BH[3]);
                MMA_BF16(oacc[j0], pl[s], BH[0], BH[1]);
                MMA_BF16(oacc[j1], pl[s], BH[2], BH[3]);
                MMA_BF16(oacc[j0], ph[s], BL[0], BL[1]);
                MMA_BF16(oacc[j1], ph[s], BL[2], BL[3]);
            }
        }
        __syncthreads();  // smem fully consumed before next stage
    }

    // ---- epilogue: normalize, split to bf16 hi/lo for the O projection ----
    float inv0 = 1.0f / l0, inv1 = 1.0f / l1;
    const size_t row0 = (size_t)b * SS + q0 + wid * 16 + (lane >> 2);
#pragma unroll
    for (int j = 0; j < 8; j++) {
        int col = h * DHD + j * 8 + ((lane & 3) << 1);
        float v0 = oacc[j][0] * inv0, v1 = oacc[j][1] * inv0;
        float v2 = oacc[j][2] * inv1, v3 = oacc[j][3] * inv1;
        uint32_t h0 = pack_bf2(v0, v1);
        uint32_t h1 = pack_bf2(v2, v3);
        __nv_bfloat162 hh0 = *(__nv_bfloat162*)&h0;
        __nv_bfloat162 hh1 = *(__nv_bfloat162*)&h1;
        *(uint32_t*)&Oh[row0 * DD + col] = h0;
        *(uint32_t*)&Ol[row0 * DD + col] =
            pack_bf2(v0 - __bfloat162float(hh0.x), v1 - __bfloat162float(hh0.y));
        *(uint32_t*)&Oh[(row0 + 8) * DD + col] = h1;
        *(uint32_t*)&Ol[(row0 + 8) * DD + col] =
            pack_bf2(v2 - __bfloat162float(hh1.x), v3 - __bfloat162float(hh1.y));
    }
}

// ---------------------------------------------------------------------------
extern "C" void kernel_launch(void* const* d_in, const int* in_sizes, int n_in,
                              void* d_out, int out_size) {
    const float* x  = (const float*)d_in[0];
    const float* Wq = (const float*)d_in[2];
    const float* bq = (const float*)d_in[3];
    const float* Wk = (const float*)d_in[4];
    const float* bk = (const float*)d_in[5];
    const float* Wv = (const float*)d_in[6];
    const float* bv = (const float*)d_in[7];
    const float* Wo = (const float*)d_in[8];
    const float* bo = (const float*)d_in[9];
    float* out = (float*)d_out;

    __nv_bfloat16 *xh, *xl, *wh, *wl, *qh, *qlp, *kh, *kl, *vh, *vl;
    cudaGetSymbolAddress((void**)&xh, g_Xh);
    cudaGetSymbolAddress((void**)&xl, g_Xl);
    cudaGetSymbolAddress((void**)&wh, g_Wh);
    cudaGetSymbolAddress((void**)&wl, g_Wl);
    cudaGetSymbolAddress((void**)&qh, g_Qh);
    cudaGetSymbolAddress((void**)&qlp, g_Ql);
    cudaGetSymbolAddress((void**)&kh, g_Kh);
    cudaGetSymbolAddress((void**)&kl, g_Kl);
    cudaGetSymbolAddress((void**)&vh, g_Vh);
    cudaGetSymbolAddress((void**)&vl, g_Vl);

    cudaFuncSetAttribute(gemm_mma_bf16x3<true>,
                         cudaFuncAttributeMaxDynamicSharedMemorySize, GS_TOTAL);
    cudaFuncSetAttribute(gemm_mma_bf16x3<false>,
                         cudaFuncAttributeMaxDynamicSharedMemorySize, GS_TOTAL);

    const int NX4 = MR * DD / 4;
    const int NW4 = DD * DD / 4;

    split_bf16<<<(NX4 + 255) / 256, 256>>>(x, xh, xl, NX4);
    split_bf16<<<(NW4 + 255) / 256, 256>>>(Wq, wh + 0 * DD * DD, wl + 0 * DD * DD, NW4);
    split_bf16<<<(NW4 + 255) / 256, 256>>>(Wk, wh + 1 * DD * DD, wl + 1 * DD * DD, NW4);
    split_bf16<<<(NW4 + 255) / 256, 256>>>(Wv, wh + 2 * DD * DD, wl + 2 * DD * DD, NW4);
    split_bf16<<<(NW4 + 255) / 256, 256>>>(Wo, wh + 3 * DD * DD, wl + 3 * DD * DD, NW4);

    dim3 gg(DD / 64, MR / 128);  // (8, 64)
    // Q projection: fold 1/sqrt(Dh) into the stored Q
    gemm_mma_bf16x3<true><<<gg, 256, GS_TOTAL>>>(
        xh, xl, wh + 0 * DD * DD, wl + 0 * DD * DD, bq, SCALE, nullptr, qh, qlp);
    gemm_mma_bf16x3<true><<<gg, 256, GS_TOTAL>>>(
        xh, xl, wh + 1 * DD * DD, wl + 1 * DD * DD, bk, 1.0f, nullptr, kh, kl);
    gemm_mma_bf16x3<true><<<gg, 256, GS_TOTAL>>>(
        xh, xl, wh + 2 * DD * DD, wl + 2 * DD * DD, bv, 1.0f, nullptr, vh, vl);

    // Attention (writes bf16 hi/lo into the x buffers, which are now free)
    dim3 ga(SS / 128, HH, BB);  // (16, 8, 4)
    attn_mma<<<ga, 256>>>(qh, qlp, kh, kl, vh, vl, xh, xl);

    // O projection -> fp32 output
    gemm_mma_bf16x3<false><<<gg, 256, GS_TOTAL>>>(
        xh, xl, wh + 3 * DD * DD, wl + 3 * DD * DD, bo, 1.0f, out, nullptr, nullptr);
}

// round 11
// speedup vs baseline: 3.6005x; 1.3049x over previous
#include <cuda_runtime.h>
#include <cuda_bf16.h>
#include <cstdint>

// Problem constants (fixed by the reference)
#define BB   4
#define SS   2048
#define DD   512
#define HH   8
#define DHD  64
#define MR   (BB * SS)        // 8192 rows
#define SCALE 0.125f          // 1/sqrt(64)

// ---------------- scratch (device globals; no allocs allowed) ---------------
__device__ __align__(16) __nv_bfloat16 g_Xh[(size_t)MR * DD];
__device__ __align__(16) __nv_bfloat16 g_Xl[(size_t)MR * DD];
__device__ __align__(16) __nv_bfloat16 g_Qh[(size_t)MR * DD];
__device__ __align__(16) __nv_bfloat16 g_Ql[(size_t)MR * DD];
__device__ __align__(16) __nv_bfloat16 g_Kh[(size_t)MR * DD];
__device__ __align__(16) __nv_bfloat16 g_Kl[(size_t)MR * DD];
__device__ __align__(16) __nv_bfloat16 g_Vh[(size_t)MR * DD];
__device__ __align__(16) __nv_bfloat16 g_Vl[(size_t)MR * DD];
__device__ __align__(16) __nv_bfloat16 g_Wh[4 * DD * DD];
__device__ __align__(16) __nv_bfloat16 g_Wl[4 * DD * DD];

// ---------------- helpers ---------------------------------------------------
__device__ __forceinline__ uint32_t smem_u32(const void* p) {
    uint32_t a;
    asm("{ .reg .u64 t; cvta.to.shared.u64 t, %1; cvt.u32.u64 %0, t; }"
        : "=r"(a) : "l"(p));
    return a;
}

#define SWZ128(o) ((o) ^ (((o) >> 3) & 0x70))

#define LDSM4(R, addr)                                                        \
    asm volatile("ldmatrix.sync.aligned.m8n8.x4.shared.b16 "                  \
                 "{%0, %1, %2, %3}, [%4];"                                    \
                 : "=r"((R)[0]), "=r"((R)[1]), "=r"((R)[2]), "=r"((R)[3])     \
                 : "r"(addr))

#define LDSM4T(R, addr)                                                       \
    asm volatile("ldmatrix.sync.aligned.m8n8.x4.trans.shared.b16 "            \
                 "{%0, %1, %2, %3}, [%4];"                                    \
                 : "=r"((R)[0]), "=r"((R)[1]), "=r"((R)[2]), "=r"((R)[3])     \
                 : "r"(addr))

#define MMA_BF16(c, a, b0, b1)                                                \
    asm volatile("mma.sync.aligned.m16n8k16.row.col.f32.bf16.bf16.f32 "       \
                 "{%0, %1, %2, %3}, {%4, %5, %6, %7}, {%8, %9}, "             \
                 "{%0, %1, %2, %3};"                                          \
                 : "+f"((c)[0]), "+f"((c)[1]), "+f"((c)[2]), "+f"((c)[3])     \
                 : "r"((a)[0]), "r"((a)[1]), "r"((a)[2]), "r"((a)[3]),        \
                   "r"(b0), "r"(b1))

#define CP16(dst, src)                                                        \
    asm volatile("cp.async.cg.shared.global [%0], [%1], 16;"                  \
                 :: "r"(dst), "l"(src))
#define CP_COMMIT() asm volatile("cp.async.commit_group;" ::: "memory")
#define CP_WAIT0()  asm volatile("cp.async.wait_group 0;" ::: "memory")
#define CP_WAIT1()  asm volatile("cp.async.wait_group 1;" ::: "memory")

__device__ __forceinline__ uint32_t pack_bf2(float a, float b) {
    __nv_bfloat162 t;
    t.x = __float2bfloat16(a);
    t.y = __float2bfloat16(b);
    return *(uint32_t*)&t;
}

// ---------------------------------------------------------------------------
// fp32 -> (hi, lo) bf16 split kernels
// ---------------------------------------------------------------------------
__global__ __launch_bounds__(256) void split_bf16(
    const float* __restrict__ in, __nv_bfloat16* __restrict__ hi,
    __nv_bfloat16* __restrict__ lo, int n4) {
    int i = blockIdx.x * blockDim.x + threadIdx.x;
    if (i >= n4) return;
    float4 v = ((const float4*)in)[i];
    __nv_bfloat16 h0 = __float2bfloat16(v.x);
    __nv_bfloat16 h1 = __float2bfloat16(v.y);
    __nv_bfloat16 h2 = __float2bfloat16(v.z);
    __nv_bfloat16 h3 = __float2bfloat16(v.w);
    __nv_bfloat162* hp = (__nv_bfloat162*)hi;
    __nv_bfloat162* lp = (__nv_bfloat162*)lo;
    hp[2 * i]     = __halves2bfloat162(h0, h1);
    hp[2 * i + 1] = __halves2bfloat162(h2, h3);
    lp[2 * i]     = __halves2bfloat162(
        __float2bfloat16(v.x - __bfloat162float(h0)),
        __float2bfloat16(v.y - __bfloat162float(h1)));
    lp[2 * i + 1] = __halves2bfloat162(
        __float2bfloat16(v.z - __bfloat162float(h2)),
        __float2bfloat16(v.w - __bfloat162float(h3)));
}

struct WSplitParams { const float* in[4]; };

__global__ __launch_bounds__(256) void split_w4(
    WSplitParams p, __nv_bfloat16* __restrict__ hi,
    __nv_bfloat16* __restrict__ lo) {
    const int w = blockIdx.y;
    const int n4 = DD * DD / 4;
    int i = blockIdx.x * blockDim.x + threadIdx.x;
    if (i >= n4) return;
    float4 v = ((const float4*)p.in[w])[i];
    __nv_bfloat16 h0 = __float2bfloat16(v.x);
    __nv_bfloat16 h1 = __float2bfloat16(v.y);
    __nv_bfloat16 h2 = __float2bfloat16(v.z);
    __nv_bfloat16 h3 = __float2bfloat16(v.w);
    __nv_bfloat162* hp = (__nv_bfloat162*)(hi + (size_t)w * DD * DD);
    __nv_bfloat162* lp = (__nv_bfloat162*)(lo + (size_t)w * DD * DD);
    hp[2 * i]     = __halves2bfloat162(h0, h1);
    hp[2 * i + 1] = __halves2bfloat162(h2, h3);
    lp[2 * i]     = __halves2bfloat162(
        __float2bfloat16(v.x - __bfloat162float(h0)),
        __float2bfloat16(v.y - __bfloat162float(h1)));
    lp[2 * i + 1] = __halves2bfloat162(
        __float2bfloat16(v.z - __bfloat162float(h2)),
        __float2bfloat16(v.w - __bfloat162float(h3)));
}

// ---------------------------------------------------------------------------
// mma.sync bf16 3-term GEMM body, cp.async double-buffered.
// CTA: 128x64 tile, 256 thr = 8 warps (4 M x 2 N), warp 32x32.
// Stage (49152 B): A_H 16K | A_L 16K | B_H 8K | B_L 8K; 2 stages = 96 KB.
// ---------------------------------------------------------------------------
#define GS_A_H 0
#define GS_A_L 16384
#define GS_B_H 32768
#define GS_B_L 40960
#define GS_STAGE 49152
#define GS_TOTAL (2 * GS_STAGE)

template <bool BF16OUT>
__device__ __forceinline__ void gemm_body(
    const __nv_bfloat16* __restrict__ Ah, const __nv_bfloat16* __restrict__ Al,
    const __nv_bfloat16* __restrict__ Bh, const __nv_bfloat16* __restrict__ Bl,
    const float* __restrict__ bias, float scale, float* __restrict__ C,
    __nv_bfloat16* __restrict__ Ch, __nv_bfloat16* __restrict__ Cl,
    char* smem) {
    const uint32_t sb = smem_u32(smem);
    const int tid = threadIdx.x;
    const int wid = tid >> 5, lane = tid & 31;
    const int wm = wid & 3, wn = wid >> 2;
    const int m0 = (int)blockIdx.y << 7;
    const int n0 = (int)blockIdx.x << 6;

    float acc[2][4][4] = {};

    const int a_row = (lane & 15);
    const int a_koff = (lane >> 4) << 3;
    const int b_mi  = lane >> 3;
    const int b_r   = lane & 7;
    const int b_jo  = b_mi >> 1;
    const int b_koff = (b_mi & 1) << 3;

    auto stage_load = [&](int kc, uint32_t base) {
#pragma unroll
        for (int v0 = 0; v0 < 1024; v0 += 256) {
            int v = v0 + tid;
            int r = v >> 3, cv = v & 7;
            size_t go = ((size_t)(m0 + r) * DD + kc) * 2 + (size_t)cv * 16;
            uint32_t bo = SWZ128((uint32_t)(r * 128 + cv * 16));
            CP16(base + GS_A_H + bo, (const char*)Ah + go);
            CP16(base + GS_A_L + bo, (const char*)Al + go);
        }
#pragma unroll
        for (int v0 = 0; v0 < 512; v0 += 256) {
            int v = v0 + tid;
            int r = v >> 3, cv = v & 7;
            size_t go = ((size_t)(n0 + r) * DD + kc) * 2 + (size_t)cv * 16;
            uint32_t bo = SWZ128((uint32_t)(r * 128 + cv * 16));
            CP16(base + GS_B_H + bo, (const char*)Bh + go);
            CP16(base + GS_B_L + bo, (const char*)Bl + go);
        }
    };

    stage_load(0, sb);
    CP_COMMIT();

    for (int c = 0; c < 8; c++) {
        const uint32_t cur = sb + (uint32_t)(c & 1) * GS_STAGE;
        if (c < 7) {
            stage_load((c + 1) << 6, sb + (uint32_t)((c + 1) & 1) * GS_STAGE);
            CP_COMMIT();
            CP_WAIT1();
        } else {
            CP_WAIT0();
        }
        __syncthreads();

#pragma unroll
        for (int ks = 0; ks < 4; ks++) {
            const int kb = ks << 4;
            uint32_t ah[2][4], al[2][4];
#pragma unroll
            for (int t = 0; t < 2; t++) {
                int row = wm * 32 + t * 16 + a_row;
                uint32_t off = SWZ128((uint32_t)(row * 128 + (kb + a_koff) * 2));
                LDSM4(ah[t], cur + GS_A_H + off);
                LDSM4(al[t], cur + GS_A_L + off);
            }
#pragma unroll
            for (int p = 0; p < 2; p++) {
                int j = p * 2 + b_jo;
                int row = wn * 32 + j * 8 + b_r;
                uint32_t off = SWZ128((uint32_t)(row * 128 + (kb + b_koff) * 2));
                uint32_t BH[4], BL[4];
                LDSM4(BH, cur + GS_B_H + off);
                LDSM4(BL, cur + GS_B_L + off);
                int j0 = p * 2, j1 = p * 2 + 1;
#pragma unroll
                for (int t = 0; t < 2; t++) {
                    MMA_BF16(acc[t][j0], ah[t], BH[0], BH[1]);
                    MMA_BF16(acc[t][j1], ah[t], BH[2], BH[3]);
                    MMA_BF16(acc[t][j0], al[t], BH[0], BH[1]);
                    MMA_BF16(acc[t][j1], al[t], BH[2], BH[3]);
                    MMA_BF16(acc[t][j0], ah[t], BL[0], BL[1]);
                    MMA_BF16(acc[t][j1], ah[t], BL[2], BL[3]);
                }
            }
        }
        __syncthreads();
    }

#pragma unroll
    for (int t = 0; t < 2; t++) {
        int row = m0 + wm * 32 + t * 16 + (lane >> 2);
#pragma unroll
        for (int j = 0; j < 4; j++) {
            int col = n0 + wn * 32 + j * 8 + ((lane & 3) << 1);
            float b0 = bias[col], b1 = bias[col + 1];
            float v0 = (acc[t][j][0] + b0) * scale;
            float v1 = (acc[t][j][1] + b1) * scale;
            float v2 = (acc[t][j][2] + b0) * scale;
            float v3 = (acc[t][j][3] + b1) * scale;
            if (BF16OUT) {
                uint32_t h01 = pack_bf2(v0, v1);
                uint32_t h23 = pack_bf2(v2, v3);
                __nv_bfloat162 hh0 = *(__nv_bfloat162*)&h01;
                __nv_bfloat162 hh1 = *(__nv_bfloat162*)&h23;
                *(uint32_t*)&Ch[(size_t)row * DD + col] = h01;
                *(uint32_t*)&Cl[(size_t)row * DD + col] =
                    pack_bf2(v0 - __bfloat162float(hh0.x),
                             v1 - __bfloat162float(hh0.y));
                *(uint32_t*)&Ch[(size_t)(row + 8) * DD + col] = h23;
                *(uint32_t*)&Cl[(size_t)(row + 8) * DD + col] =
                    pack_bf2(v2 - __bfloat162float(hh1.x),
                             v3 - __bfloat162float(hh1.y));
            } else {
                float2 o0 = {v0, v1};
                float2 o1 = {v2, v3};
                *(float2*)&C[(size_t)row * DD + col] = o0;
                *(float2*)&C[(size_t)(row + 8) * DD + col] = o1;
            }
        }
    }
}

struct QKVParams {
    const __nv_bfloat16* Bh[3];
    const __nv_bfloat16* Bl[3];
    const float* bias[3];
    float scale[3];
    __nv_bfloat16* Ch[3];
    __nv_bfloat16* Cl[3];
};

__global__ __launch_bounds__(256) void gemm_qkv(
    const __nv_bfloat16* __restrict__ Ah, const __nv_bfloat16* __restrict__ Al,
    QKVParams p) {
    extern __shared__ char smem[];
    const int z = blockIdx.z;
    gemm_body<true>(Ah, Al, p.Bh[z], p.Bl[z], p.bias[z], p.scale[z], nullptr,
                    p.Ch[z], p.Cl[z], smem);
}

__global__ __launch_bounds__(256) void gemm_o(
    const __nv_bfloat16* __restrict__ Ah, const __nv_bfloat16* __restrict__ Al,
    const __nv_bfloat16* __restrict__ Bh, const __nv_bfloat16* __restrict__ Bl,
    const float* __restrict__ bias, float* __restrict__ C) {
    extern __shared__ char smem[];
    gemm_body<false>(Ah, Al, Bh, Bl, bias, 1.0f, C, nullptr, nullptr, smem);
}

// ---------------------------------------------------------------------------
// Flash attention (causal) on mma.sync bf16 3-term, cp.async double-buffered.
// CTA: 128 queries x one (b,h); 8 warps, each owns 16 rows x all 64 cols.
// Stage (32 KB): Kh 8K | Kl 8K | Vh 8K | Vl 8K; 2 stages = 64 KB dynamic.
// Tile t lives in stage (t+1)&1; Q staged in stage 0's memory up front.
// ---------------------------------------------------------------------------
#define AS_KH 0
#define AS_KL 8192
#define AS_VH 16384
#define AS_VL 24576
#define AS_STAGE 32768
#define AS_TOTAL (2 * AS_STAGE)

__global__ __launch_bounds__(256) void attn_mma(
    const __nv_bfloat16* __restrict__ Qh, const __nv_bfloat16* __restrict__ Ql,
    const __nv_bfloat16* __restrict__ Kh, const __nv_bfloat16* __restrict__ Kl,
    const __nv_bfloat16* __restrict__ Vh, const __nv_bfloat16* __restrict__ Vl,
    __nv_bfloat16* __restrict__ Oh, __nv_bfloat16* __restrict__ Ol) {
    extern __shared__ char smem[];
    const uint32_t sb = smem_u32(smem);
    const int tid = threadIdx.x;
    const int wid = tid >> 5, lane = tid & 31;
    const int qt = (int)gridDim.x - 1 - (int)blockIdx.x;  // heavy tiles first
    const int h = blockIdx.y, b = blockIdx.z;
    const int q0 = qt << 7;

    const size_t head_off = (size_t)b * SS * DD + h * DHD;
    const __nv_bfloat16* Qhp = Qh + head_off + (size_t)q0 * DD;
    const __nv_bfloat16* Qlp = Ql + head_off + (size_t)q0 * DD;
    const __nv_bfloat16* Khp = Kh + head_off;
    const __nv_bfloat16* Klp = Kl + head_off;
    const __nv_bfloat16* Vhp = Vh + head_off;
    const __nv_bfloat16* Vlp = Vl + head_off;

    const int ntiles = 2 * qt + 2;

    auto stage_kv = [&](int k0, uint32_t base) {
#pragma unroll
        for (int v0 = 0; v0 < 512; v0 += 256) {
            int v = v0 + tid;
            int r = v >> 3, c = v & 7;
            uint32_t bo = SWZ128((uint32_t)(r * 128 + c * 16));
            size_t g = ((size_t)(k0 + r) * DD + c * 8) * 2;
            CP16(base + AS_KH + bo, (const char*)Khp + g);
            CP16(base + AS_KL + bo, (const char*)Klp + g);
            CP16(base + AS_VH + bo, (const char*)Vhp + g);
            CP16(base + AS_VL + bo, (const char*)Vlp + g);
        }
    };

    // --- Stage Q into stage-0 memory, prefetch tile 0 into stage 1 ---------
    for (int v = tid; v < 1024; v += 256) {
        int r = v >> 3, c = v & 7;
        uint32_t bo = SWZ128((uint32_t)(r * 128 + c * 16));
        *(uint4*)(smem + bo) = *(const uint4*)(Qhp + (size_t)r * DD + c * 8);
        *(uint4*)(smem + 16384 + bo) = *(const uint4*)(Qlp + (size_t)r * DD + c * 8);
    }
    __syncthreads();
    stage_kv(0, sb + AS_STAGE);  // tile 0 -> stage 1 (overlaps Q frag reads)
    CP_COMMIT();

    uint32_t qh[4][4], ql[4][4];
    {
        const int arow = wid * 16 + (lane & 15);
        const int akoff = (lane >> 4) << 3;
#pragma unroll
        for (int s = 0; s < 4; s++) {
            uint32_t off = SWZ128((uint32_t)(arow * 128 + (s * 16 + akoff) * 2));
            LDSM4(qh[s], sb + off);
            LDSM4(ql[s], sb + 16384 + off);
        }
    }
    __syncthreads();  // Q fully consumed; stage 0 free for tile 1's cp.async

    const int b_mi = lane >> 3;
    const int b_r = lane & 7;
    const int b_jo = b_mi >> 1;
    const int b_koff = (b_mi & 1) << 3;

    float m0 = -1e30f, m1 = -1e30f, l0 = 0.f, l1 = 0.f;
    float oacc[8][4] = {};

    for (int t = 0; t < ntiles; t++) {
        const int k0 = t << 6;
        const uint32_t cur = sb + (uint32_t)((t + 1) & 1) * AS_STAGE;
        if (t + 1 < ntiles) {
            stage_kv((t + 1) << 6, sb + (uint32_t)(t & 1) * AS_STAGE);
            CP_COMMIT();
            CP_WAIT1();
        } else {
            CP_WAIT0();
        }
        __syncthreads();

        // ---- S = Q K^T (3-term) ----
        float sacc[8][4] = {};
#pragma unroll
        for (int s = 0; s < 4; s++) {
#pragma unroll
            for (int p = 0; p < 4; p++) {
                int row = p * 16 + b_jo * 8 + b_r;  // key row
                uint32_t off =
                    SWZ128((uint32_t)(row * 128 + (s * 16 + b_koff) * 2));
                uint32_t BH[4], BL[4];
                LDSM4(BH, cur + AS_KH + off);
                LDSM4(BL, cur + AS_KL + off);
                int j0 = p * 2, j1 = p * 2 + 1;
                MMA_BF16(sacc[j0], qh[s], BH[0], BH[1]);
                MMA_BF16(sacc[j1], qh[s], BH[2], BH[3]);
                MMA_BF16(sacc[j0], ql[s], BH[0], BH[1]);
                MMA_BF16(sacc[j1], ql[s], BH[2], BH[3]);
                MMA_BF16(sacc[j0], qh[s], BL[0], BL[1]);
                MMA_BF16(sacc[j1], qh[s], BL[2], BL[3]);
            }
        }

        // ---- causal mask (only the last two tiles touch the diagonal) ----
        if (t >= 2 * qt) {
            const int rbase = wid * 16 + (lane >> 2);
            const int cbase = (lane & 3) << 1;
#pragma unroll
            for (int j = 0; j < 8; j++)
#pragma unroll
                for (int c = 0; c < 4; c++) {
                    int row = rbase + ((c >> 1) << 3);
                    int col = j * 8 + cbase + (c & 1);
                    if (k0 + col > q0 + row) sacc[j][c] = -1e30f;
                }
        }

        // ---- online softmax (rows live in quads; xor 1,2 shuffles) ----
        float rmax0 = -1e30f, rmax1 = -1e30f;
#pragma unroll
        for (int j = 0; j < 8; j++) {
            rmax0 = fmaxf(rmax0, fmaxf(sacc[j][0], sacc[j][1]));
            rmax1 = fmaxf(rmax1, fmaxf(sacc[j][2], sacc[j][3]));
        }
        rmax0 = fmaxf(rmax0, __shfl_xor_sync(0xffffffffu, rmax0, 1));
        rmax0 = fmaxf(rmax0, __shfl_xor_sync(0xffffffffu, rmax0, 2));
        rmax1 = fmaxf(rmax1, __shfl_xor_sync(0xffffffffu, rmax1, 1));
        rmax1 = fmaxf(rmax1, __shfl_xor_sync(0xffffffffu, rmax1, 2));
        float mn0 = fmaxf(m0, rmax0), mn1 = fmaxf(m1, rmax1);
        float corr0 = __expf(m0 - mn0), corr1 = __expf(m1 - mn1);
        m0 = mn0; m1 = mn1;

        float sum0 = 0.f, sum1 = 0.f;
        uint32_t ph[4][4], pl[4][4];
#pragma unroll
        for (int s = 0; s < 4; s++) {
            int j0 = 2 * s, j1 = 2 * s + 1;
            float e00 = __expf(sacc[j0][0] - mn0);
            float e01 = __expf(sacc[j0][1] - mn0);
            float e02 = __expf(sacc[j0][2] - mn1);
            float e03 = __expf(sacc[j0][3] - mn1);
            float e10 = __expf(sacc[j1][0] - mn0);
            float e11 = __expf(sacc[j1][1] - mn0);
            float e12 = __expf(sacc[j1][2] - mn1);
            float e13 = __expf(sacc[j1][3] - mn1);
            sum0 += e00 + e01 + e10 + e11;
            sum1 += e02 + e03 + e12 + e13;
            ph[s][0] = pack_bf2(e00, e01);
            ph[s][1] = pack_bf2(e02, e03);
            ph[s][2] = pack_bf2(e10, e11);
            ph[s][3] = pack_bf2(e12, e13);
            __nv_bfloat162 h0 = *(__nv_bfloat162*)&ph[s][0];
            __nv_bfloat162 h1 = *(__nv_bfloat162*)&ph[s][1];
            __nv_bfloat162 h2 = *(__nv_bfloat162*)&ph[s][2];
            __nv_bfloat162 h3 = *(__nv_bfloat162*)&ph[s][3];
            pl[s][0] = pack_bf2(e00 - __bfloat162float(h0.x),
                                e01 - __bfloat162float(h0.y));
            pl[s][1] = pack_bf2(e02 - __bfloat162float(h1.x),
                                e03 - __bfloat162float(h1.y));
            pl[s][2] = pack_bf2(e10 - __bfloat162float(h2.x),
                                e11 - __bfloat162float(h2.y));
            pl[s][3] = pack_bf2(e12 - __bfloat162float(h3.x),
                                e13 - __bfloat162float(h3.y));
        }
        sum0 += __shfl_xor_sync(0xffffffffu, sum0, 1);
        sum0 += __shfl_xor_sync(0xffffffffu, sum0, 2);
        sum1 += __shfl_xor_sync(0xffffffffu, sum1, 1);
        sum1 += __shfl_xor_sync(0xffffffffu, sum1, 2);
        l0 = l0 * corr0 + sum0;
        l1 = l1 * corr1 + sum1;
#pragma unroll
        for (int j = 0; j < 8; j++) {
            oacc[j][0] *= corr0; oacc[j][1] *= corr0;
            oacc[j][2] *= corr1; oacc[j][3] *= corr1;
        }

        // ---- O += P V (3-term); V via ldmatrix.trans from [key][d] ----
#pragma unroll
        for (int s = 0; s < 4; s++) {
#pragma unroll
            for (int p = 0; p < 4; p++) {
                int krow = s * 16 + ((b_mi & 1) << 3) + b_r;
                int colb = (p * 2 + b_jo) * 16;
                uint32_t off = SWZ128((uint32_t)(krow * 128 + colb));
                uint32_t BH[4], BL[4];
                LDSM4T(BH, cur + AS_VH + off);
                LDSM4T(BL, cur + AS_VL + off);
                int j0 = p * 2, j1 = p * 2 + 1;
                MMA_BF16(oacc[j0], ph[s], BH[0], BH[1]);
                MMA_BF16(oacc[j1], ph[s], BH[2], BH[3]);
                MMA_BF16(oacc[j0], pl[s], BH[0], BH[1]);
                MMA_BF16(oacc[j1], pl[s], BH[2], BH[3]);
                MMA_BF16(oacc[j0], ph[s], BL[0], BL[1]);
                MMA_BF16(oacc[j1], ph[s], BL[2], BL[3]);
            }
        }
        __syncthreads();  // cur fully consumed before next iter overwrites it
    }

    // ---- epilogue: normalize, split to bf16 hi/lo for the O projection ----
    float inv0 = 1.0f / l0, inv1 = 1.0f / l1;
    const size_t row0 = (size_t)b * SS + q0 + wid * 16 + (lane >> 2);
#pragma unroll
    for (int j = 0; j < 8; j++) {
        int col = h * DHD + j * 8 + ((lane & 3) << 1);
        float v0 = oacc[j][0] * inv0, v1 = oacc[j][1] * inv0;
        float v2 = oacc[j][2] * inv1, v3 = oacc[j][3] * inv1;
        uint32_t h0 = pack_bf2(v0, v1);
        uint32_t h1 = pack_bf2(v2, v3);
        __nv_bfloat162 hh0 = *(__nv_bfloat162*)&h0;
        __nv_bfloat162 hh1 = *(__nv_bfloat162*)&h1;
        *(uint32_t*)&Oh[row0 * DD + col] = h0;
        *(uint32_t*)&Ol[row0 * DD + col] =
            pack_bf2(v0 - __bfloat162float(hh0.x), v1 - __bfloat162float(hh0.y));
        *(uint32_t*)&Oh[(row0 + 8) * DD + col] = h1;
        *(uint32_t*)&Ol[(row0 + 8) * DD + col] =
            pack_bf2(v2 - __bfloat162float(hh1.x), v3 - __bfloat162float(hh1.y));
    }
}

// ---------------------------------------------------------------------------
extern "C" void kernel_launch(void* const* d_in, const int* in_sizes, int n_in,
                              void* d_out, int out_size) {
    const float* x  = (const float*)d_in[0];
    const float* Wq = (const float*)d_in[2];
    const float* bq = (const float*)d_in[3];
    const float* Wk = (const float*)d_in[4];
    const float* bk = (const float*)d_in[5];
    const float* Wv = (const float*)d_in[6];
    const float* bv = (const float*)d_in[7];
    const float* Wo = (const float*)d_in[8];
    const float* bo = (const float*)d_in[9];
    float* out = (float*)d_out;

    __nv_bfloat16 *xh, *xl, *wh, *wl, *qh, *qlp, *kh, *kl, *vh, *vl;
    cudaGetSymbolAddress((void**)&xh, g_Xh);
    cudaGetSymbolAddress((void**)&xl, g_Xl);
    cudaGetSymbolAddress((void**)&wh, g_Wh);
    cudaGetSymbolAddress((void**)&wl, g_Wl);
    cudaGetSymbolAddress((void**)&qh, g_Qh);
    cudaGetSymbolAddress((void**)&qlp, g_Ql);
    cudaGetSymbolAddress((void**)&kh, g_Kh);
    cudaGetSymbolAddress((void**)&kl, g_Kl);
    cudaGetSymbolAddress((void**)&vh, g_Vh);
    cudaGetSymbolAddress((void**)&vl, g_Vl);

    cudaFuncSetAttribute(gemm_qkv,
                         cudaFuncAttributeMaxDynamicSharedMemorySize, GS_TOTAL);
    cudaFuncSetAttribute(gemm_o,
                         cudaFuncAttributeMaxDynamicSharedMemorySize, GS_TOTAL);
    cudaFuncSetAttribute(attn_mma,
                         cudaFuncAttributeMaxDynamicSharedMemorySize, AS_TOTAL);

    const int NX4 = MR * DD / 4;
    const int NW4 = DD * DD / 4;

    split_bf16<<<(NX4 + 255) / 256, 256>>>(x, xh, xl, NX4);
    WSplitParams wp;
    wp.in[0] = Wq; wp.in[1] = Wk; wp.in[2] = Wv; wp.in[3] = Wo;
    split_w4<<<dim3((NW4 + 255) / 256, 4), 256>>>(wp, wh, wl);

    // Q/K/V projections fused into one launch (z selects the projection)
    QKVParams qp;
    qp.Bh[0] = wh + 0 * DD * DD; qp.Bl[0] = wl + 0 * DD * DD;
    qp.Bh[1] = wh + 1 * DD * DD; qp.Bl[1] = wl + 1 * DD * DD;
    qp.Bh[2] = wh + 2 * DD * DD; qp.Bl[2] = wl + 2 * DD * DD;
    qp.bias[0] = bq; qp.bias[1] = bk; qp.bias[2] = bv;
    qp.scale[0] = SCALE; qp.scale[1] = 1.0f; qp.scale[2] = 1.0f;
    qp.Ch[0] = qh; qp.Cl[0] = qlp;
    qp.Ch[1] = kh; qp.Cl[1] = kl;
    qp.Ch[2] = vh; qp.Cl[2] = vl;
    gemm_qkv<<<dim3(DD / 64, MR / 128, 3), 256, GS_TOTAL>>>(xh, xl, qp);

    // Attention (writes bf16 hi/lo into the x buffers, which are now free)
    dim3 ga(SS / 128, HH, BB);  // (16, 8, 4)
    attn_mma<<<ga, 256, AS_TOTAL>>>(qh, qlp, kh, kl, vh, vl, xh, xl);

    // O projection -> fp32 output
    gemm_o<<<dim3(DD / 64, MR / 128), 256, GS_TOTAL>>>(
        xh, xl, wh + 3 * DD * DD, wl + 3 * DD * DD, bo, out);
}